// round 2
// baseline (speedup 1.0000x reference)
#include <cuda_runtime.h>
#include <cstdint>
#include <cstddef>

namespace {

constexpr int kB   = 4096;
constexpr int kN   = 64;
constexpr int kOBS = 192;
constexpr int kACT = 64;
constexpr int kIN  = 256;
constexpr int kD   = 128;
constexpr int kFH  = 64;
constexpr int kFO  = 64;

// SMEM strides (all ≡ 4 mod 32 -> conflict-free fragment loads)
constexpr int SA_LD = 260;
constexpr int E_LD  = 132;
constexpr int W_LD  = 68;

// SMEM pool layout (floats)
constexpr int OFF_E  = 0;            // e / later x      : 64*132 = 8448
constexpr int OFF_EQ = 8448;         // eq               : 8448
constexpr int OFF_R  = 16896;        // sa (16640) -> later q(8448)+k(8448) -> later h(4352)
constexpr int OFF_Q  = 16896;
constexpr int OFF_K  = 25344;
constexpr int OFF_V  = 33792;        // v^T : 128*68 = 8704
constexpr int OFF_W  = 42496;        // weight-chunk stage / softmax matrix : 8704
constexpr int SMEM_FLOATS = 51200;   // 204800 bytes
constexpr int SMEM_BYTES  = SMEM_FLOATS * 4;

__device__ __forceinline__ float f2tf_f(float x) {
  uint32_t u;
  asm("cvt.rna.tf32.f32 %0, %1;" : "=r"(u) : "f"(x));
  return __uint_as_float(u);
}

__device__ __forceinline__ void mma8(float (&d)[4], const uint32_t (&a)[4],
                                     const uint32_t (&b)[2]) {
  asm volatile(
      "mma.sync.aligned.m16n8k8.row.col.f32.tf32.tf32.f32 "
      "{%0,%1,%2,%3}, {%4,%5,%6,%7}, {%8,%9}, {%0,%1,%2,%3};\n"
      : "+f"(d[0]), "+f"(d[1]), "+f"(d[2]), "+f"(d[3])
      : "r"(a[0]), "r"(a[1]), "r"(a[2]), "r"(a[3]), "r"(b[0]), "r"(b[1]));
}

// C[64][NT*8*4 cols] += A[64][K] * B[Ncols][K]^T  (8 warps: wm in {0,1}, wn in {0..3})
template <int NT>
__device__ __forceinline__ void mma_block(const float* As, int lda,
                                          const float* Bs, int ldb, int Kc,
                                          float (&d)[2][NT][4],
                                          int lane, int wm, int wn) {
  const float* Aw = As + (wm * 32) * lda;
  const float* Bw = Bs + (wn * NT * 8) * ldb;
  const int gr = lane >> 2, gc = lane & 3;
  for (int k0 = 0; k0 < Kc; k0 += 8) {
    uint32_t a[2][4];
#pragma unroll
    for (int mt = 0; mt < 2; mt++) {
      const float* p = Aw + (mt * 16 + gr) * lda + k0 + gc;
      a[mt][0] = __float_as_uint(p[0]);
      a[mt][1] = __float_as_uint(p[8 * lda]);
      a[mt][2] = __float_as_uint(p[4]);
      a[mt][3] = __float_as_uint(p[8 * lda + 4]);
    }
#pragma unroll
    for (int nt = 0; nt < NT; nt++) {
      uint32_t bf[2];
      const float* p = Bw + (nt * 8 + gr) * ldb + k0 + gc;
      bf[0] = __float_as_uint(p[0]);
      bf[1] = __float_as_uint(p[4]);
#pragma unroll
      for (int mt = 0; mt < 2; mt++) mma8(d[mt][nt], a[mt], bf);
    }
  }
}

template <int NT, class F>
__device__ __forceinline__ void for_each_acc(float (&d)[2][NT][4], int lane,
                                             int wm, int wn, F f) {
  const int gr = lane >> 2, gc = (lane & 3) * 2;
#pragma unroll
  for (int mt = 0; mt < 2; mt++)
#pragma unroll
    for (int nt = 0; nt < NT; nt++)
#pragma unroll
      for (int i = 0; i < 4; i++) {
        int row = wm * 32 + mt * 16 + gr + ((i >> 1) << 3);
        int col = wn * NT * 8 + nt * 8 + gc + (i & 1);
        f(row, col, d[mt][nt][i]);
      }
}

template <int NT>
__device__ __forceinline__ void zero_acc(float (&d)[2][NT][4]) {
#pragma unroll
  for (int mt = 0; mt < 2; mt++)
#pragma unroll
    for (int nt = 0; nt < NT; nt++)
#pragma unroll
      for (int i = 0; i < 4; i++) d[mt][nt][i] = 0.f;
}

__global__ __launch_bounds__(256, 1)
void critic_kernel(const float* __restrict__ states,
                   const float* __restrict__ actions,
                   const float* __restrict__ W_embed,
                   const float* __restrict__ b_embed,
                   const float* __restrict__ W_k,
                   const float* __restrict__ W_q,
                   const float* __restrict__ W_v,
                   const float* __restrict__ W_embed_q,
                   const float* __restrict__ b_embed_q,
                   const float* __restrict__ W_f1,
                   const float* __restrict__ W_f2,
                   float* __restrict__ outV,
                   float* __restrict__ outW) {
  extern __shared__ float smem[];
  const int b = blockIdx.x;
  const int tid = threadIdx.x;
  const int lane = tid & 31;
  const int warp = tid >> 5;
  const int wm = warp >> 2, wn = warp & 3;

  float* E  = smem + OFF_E;
  float* EQ = smem + OFF_EQ;
  float* SA = smem + OFF_R;
  float* Qm = smem + OFF_Q;
  float* Km = smem + OFF_K;
  float* VT = smem + OFF_V;
  float* WG = smem + OFF_W;

  // ---- load sa = concat(states, actions), tf32-rounded
  {
    const float* st = states + (size_t)b * kN * kOBS;
    const float* ac = actions + (size_t)b * kN * kACT;
    for (int i = tid; i < kN * kIN; i += 256) {
      int t = i >> 8, c = i & 255;
      float v = (c < kOBS) ? st[t * kOBS + c] : ac[t * kACT + (c - kOBS)];
      SA[t * SA_LD + c] = f2tf_f(v);
    }
  }

  auto load_w = [&](const float* W, int On, int Kfull, int k0) {
    for (int i = tid; i < On * 64; i += 256) {
      int o = i >> 6, k = i & 63;
      WG[o * W_LD + k] = f2tf_f(W[o * Kfull + k0 + k]);
    }
  };

  float d4[2][4][4];
  float d2[2][2][4];

  // ---- e = lrelu(sa @ W_embed^T + b_embed)  [64,128]
  zero_acc(d4);
  for (int k0 = 0; k0 < kIN; k0 += 64) {
    __syncthreads();
    load_w(W_embed, 128, kIN, k0);
    __syncthreads();
    mma_block<4>(SA + k0, SA_LD, WG, W_LD, 64, d4, lane, wm, wn);
  }
  for_each_acc<4>(d4, lane, wm, wn, [&](int r, int c, float v) {
    v += b_embed[c];
    v = v > 0.f ? v : 0.01f * v;
    E[r * E_LD + c] = f2tf_f(v);
  });

  // ---- eq = lrelu(sa @ W_embed_q^T + b_embed_q)  [64,128]
  zero_acc(d4);
  for (int k0 = 0; k0 < kIN; k0 += 64) {
    __syncthreads();
    load_w(W_embed_q, 128, kIN, k0);
    __syncthreads();
    mma_block<4>(SA + k0, SA_LD, WG, W_LD, 64, d4, lane, wm, wn);
  }
  for_each_acc<4>(d4, lane, wm, wn, [&](int r, int c, float v) {
    v += b_embed_q[c];
    v = v > 0.f ? v : 0.01f * v;
    EQ[r * E_LD + c] = f2tf_f(v);
  });

  // ---- q = e @ W_q^T   (writes into old sa region; safe: sync precedes)
  zero_acc(d4);
  for (int k0 = 0; k0 < kD; k0 += 64) {
    __syncthreads();
    load_w(W_q, 128, kD, k0);
    __syncthreads();
    mma_block<4>(E + k0, E_LD, WG, W_LD, 64, d4, lane, wm, wn);
  }
  for_each_acc<4>(d4, lane, wm, wn, [&](int r, int c, float v) {
    Qm[r * E_LD + c] = f2tf_f(v);
  });

  // ---- k = e @ W_k^T
  zero_acc(d4);
  for (int k0 = 0; k0 < kD; k0 += 64) {
    __syncthreads();
    load_w(W_k, 128, kD, k0);
    __syncthreads();
    mma_block<4>(E + k0, E_LD, WG, W_LD, 64, d4, lane, wm, wn);
  }
  for_each_acc<4>(d4, lane, wm, wn, [&](int r, int c, float v) {
    Km[r * E_LD + c] = f2tf_f(v);
  });

  // ---- v = e @ W_v^T, stored transposed: VT[d][t]
  zero_acc(d4);
  for (int k0 = 0; k0 < kD; k0 += 64) {
    __syncthreads();
    load_w(W_v, 128, kD, k0);
    __syncthreads();
    mma_block<4>(E + k0, E_LD, WG, W_LD, 64, d4, lane, wm, wn);
  }
  for_each_acc<4>(d4, lane, wm, wn, [&](int r, int c, float v) {
    VT[c * W_LD + r] = f2tf_f(v);
  });

  __syncthreads();

  // ---- scores = q @ k^T / sqrt(D) -> WG (fp32, 64x64)
  zero_acc(d2);
  mma_block<2>(Qm, E_LD, Km, E_LD, kD, d2, lane, wm, wn);
  for_each_acc<2>(d2, lane, wm, wn, [&](int r, int c, float v) {
    WG[r * W_LD + c] = v * 0.08838834764831845f;
  });
  __syncthreads();

  // ---- row softmax; write weight to gmem (fp32) + tf32 copy in smem
  {
    const int r = tid >> 2;
    const int c0 = (tid & 3) * 16;
    float* wrow = WG + r * W_LD + c0;
    float mx = -3.0e38f;
#pragma unroll
    for (int j = 0; j < 16; j++) mx = fmaxf(mx, wrow[j]);
    mx = fmaxf(mx, __shfl_xor_sync(0xffffffffu, mx, 1));
    mx = fmaxf(mx, __shfl_xor_sync(0xffffffffu, mx, 2));
    float ex[16];
    float sum = 0.f;
#pragma unroll
    for (int j = 0; j < 16; j++) {
      ex[j] = __expf(wrow[j] - mx);
      sum += ex[j];
    }
    sum += __shfl_xor_sync(0xffffffffu, sum, 1);
    sum += __shfl_xor_sync(0xffffffffu, sum, 2);
    float inv = 1.f / sum;
    float* og = outW + ((size_t)b * kN + r) * kN + c0;
#pragma unroll
    for (int j = 0; j < 16; j++) {
      float w = ex[j] * inv;
      og[j] = w;
      wrow[j] = f2tf_f(w);
    }
  }
  __syncthreads();

  // ---- x = weight @ v   (A = WG [64][64], B = VT [128][64]) -> E region
  zero_acc(d4);
  mma_block<4>(WG, W_LD, VT, W_LD, kN, d4, lane, wm, wn);
  for_each_acc<4>(d4, lane, wm, wn, [&](int r, int c, float v) {
    E[r * E_LD + c] = f2tf_f(v);
  });

  // ---- h = lrelu([eq, x] @ W_f1^T)  [64,64]
  zero_acc(d2);
  for (int k0 = 0; k0 < kD; k0 += 64) {
    __syncthreads();
    load_w(W_f1, 64, 2 * kD, k0);
    __syncthreads();
    mma_block<2>(EQ + k0, E_LD, WG, W_LD, 64, d2, lane, wm, wn);
  }
  for (int k0 = 0; k0 < kD; k0 += 64) {
    __syncthreads();
    load_w(W_f1, 64, 2 * kD, kD + k0);
    __syncthreads();
    mma_block<2>(E + k0, E_LD, WG, W_LD, 64, d2, lane, wm, wn);
  }
  float* H = smem + OFF_R;  // q/k regions are dead now
  for_each_acc<2>(d2, lane, wm, wn, [&](int r, int c, float v) {
    v = v > 0.f ? v : 0.01f * v;
    H[r * W_LD + c] = f2tf_f(v);
  });

  // ---- Value = h @ W_f2^T -> gmem (fp32)
  zero_acc(d2);
  __syncthreads();
  load_w(W_f2, 64, kFH, 0);
  __syncthreads();
  mma_block<2>(H, W_LD, WG, W_LD, kFH, d2, lane, wm, wn);
  for_each_acc<2>(d2, lane, wm, wn, [&](int r, int c, float v) {
    outV[((size_t)b * kN + r) * kFO + c] = v;
  });
}

}  // namespace

extern "C" void kernel_launch(void* const* d_in, const int* in_sizes, int n_in,
                              void* d_out, int out_size) {
  (void)in_sizes; (void)n_in; (void)out_size;
  const float* states    = (const float*)d_in[0];
  const float* actions   = (const float*)d_in[1];
  const float* W_embed   = (const float*)d_in[2];
  const float* b_embed   = (const float*)d_in[3];
  const float* W_k       = (const float*)d_in[4];
  const float* W_q       = (const float*)d_in[5];
  const float* W_v       = (const float*)d_in[6];
  const float* W_embed_q = (const float*)d_in[7];
  const float* b_embed_q = (const float*)d_in[8];
  const float* W_f1      = (const float*)d_in[9];
  const float* W_f2      = (const float*)d_in[10];

  float* outV = (float*)d_out;                          // Value [B,N,64] first
  float* outW = outV + (size_t)kB * kN * kFO;           // weight [B,N,N] second

  cudaFuncSetAttribute(critic_kernel,
                       cudaFuncAttributeMaxDynamicSharedMemorySize, SMEM_BYTES);
  critic_kernel<<<kB, 256, SMEM_BYTES>>>(states, actions, W_embed, b_embed,
                                         W_k, W_q, W_v, W_embed_q, b_embed_q,
                                         W_f1, W_f2, outV, outW);
}

// round 3
// speedup vs baseline: 1.7575x; 1.7575x over previous
#include <cuda_runtime.h>
#include <cstdint>
#include <cstddef>

namespace {

constexpr int kB   = 4096;
constexpr int kN   = 64;
constexpr int kOBS = 192;
constexpr int kACT = 64;
constexpr int kIN  = 256;
constexpr int kD   = 128;
constexpr int kFH  = 64;
constexpr int kFO  = 64;

constexpr int kThreads = 512;  // 16 warps: wm in {0,1}, wn in {0..7}

// SMEM strides (all ≡ 4 mod 32 -> conflict-free fragment loads)
constexpr int SA_LD = 260;
constexpr int E_LD  = 132;
constexpr int S_LD  = 68;
constexpr int WG_LD = 36;   // staged weight chunk: [On rows][32 k-cols]

// SMEM pool layout (floats)
// Region A (SA): sa [64x260]=16640; later aliased: T [64x132]=8448 at +0,
//                SC [64x68]=4352 at +8448, H [64x68]=4352 at +0 (after x).
constexpr int OFF_SA = 0;
constexpr int OFF_T  = 0;
constexpr int OFF_SC = 8448;
constexpr int OFF_H  = 0;
constexpr int OFF_E  = 16640;          // e, later x  [64x132]
constexpr int OFF_EQ = 25088;          // eq          [64x132]
constexpr int OFF_VT = 33536;          // v^T         [128x68] = 8704
constexpr int OFF_W0 = 42240;          // weight stage buf0 [128x36] = 4608
constexpr int OFF_W1 = 46848;          // weight stage buf1 [128x36] = 4608
constexpr int SMEM_FLOATS = 51456;     // 205824 bytes
constexpr int SMEM_BYTES  = SMEM_FLOATS * 4;

__device__ float gMt[kD * kD];  // Mt[j][i] = sum_d Wq[d][i] * Wk[d][j]

__device__ __forceinline__ float f2tf_f(float x) {
  uint32_t u;
  asm("cvt.rna.tf32.f32 %0, %1;" : "=r"(u) : "f"(x));
  return __uint_as_float(u);
}

__device__ __forceinline__ void mma8(float (&d)[4], const uint32_t (&a)[4],
                                     const uint32_t (&b)[2]) {
  asm volatile(
      "mma.sync.aligned.m16n8k8.row.col.f32.tf32.tf32.f32 "
      "{%0,%1,%2,%3}, {%4,%5,%6,%7}, {%8,%9}, {%0,%1,%2,%3};\n"
      : "+f"(d[0]), "+f"(d[1]), "+f"(d[2]), "+f"(d[3])
      : "r"(a[0]), "r"(a[1]), "r"(a[2]), "r"(a[3]), "r"(b[0]), "r"(b[1]));
}

// C[64 rows][NT*8 cols per warp] += A[64][Kc] * B[cols][Kc]^T
// 16 warps: wm in {0,1} -> 32-row halves; wn in {0..7} -> NT*8-col slices.
template <int NT>
__device__ __forceinline__ void mma_block(const float* As, int lda,
                                          const float* Bs, int ldb, int Kc,
                                          float (&d)[2][NT][4],
                                          int lane, int wm, int wn) {
  const float* Aw = As + (wm * 32) * lda;
  const float* Bw = Bs + (wn * NT * 8) * ldb;
  const int gr = lane >> 2, gc = lane & 3;
  for (int k0 = 0; k0 < Kc; k0 += 8) {
    uint32_t a[2][4];
#pragma unroll
    for (int mt = 0; mt < 2; mt++) {
      const float* p = Aw + (mt * 16 + gr) * lda + k0 + gc;
      a[mt][0] = __float_as_uint(p[0]);
      a[mt][1] = __float_as_uint(p[8 * lda]);
      a[mt][2] = __float_as_uint(p[4]);
      a[mt][3] = __float_as_uint(p[8 * lda + 4]);
    }
#pragma unroll
    for (int nt = 0; nt < NT; nt++) {
      uint32_t bf[2];
      const float* p = Bw + (nt * 8 + gr) * ldb + k0 + gc;
      bf[0] = __float_as_uint(p[0]);
      bf[1] = __float_as_uint(p[4]);
#pragma unroll
      for (int mt = 0; mt < 2; mt++) mma8(d[mt][nt], a[mt], bf);
    }
  }
}

template <int NT, class F>
__device__ __forceinline__ void for_each_acc(float (&d)[2][NT][4], int lane,
                                             int wm, int wn, F f) {
  const int gr = lane >> 2, gc = (lane & 3) * 2;
#pragma unroll
  for (int mt = 0; mt < 2; mt++)
#pragma unroll
    for (int nt = 0; nt < NT; nt++)
#pragma unroll
      for (int i = 0; i < 4; i++) {
        int row = wm * 32 + mt * 16 + gr + ((i >> 1) << 3);
        int col = wn * NT * 8 + nt * 8 + gc + (i & 1);
        f(row, col, d[mt][nt][i]);
      }
}

template <int NT>
__device__ __forceinline__ void zero_acc(float (&d)[2][NT][4]) {
#pragma unroll
  for (int mt = 0; mt < 2; mt++)
#pragma unroll
    for (int nt = 0; nt < NT; nt++)
#pragma unroll
      for (int i = 0; i < 4; i++) d[mt][nt][i] = 0.f;
}

// ---- weight chunk staging: [On rows] x [32 k-cols], ldg->regs then sts
__device__ __forceinline__ void ldg_chunk(float (&r)[8], const float* W,
                                          int On, int Kfull, int k0, int tid) {
  const int total = On * 32;
#pragma unroll
  for (int j = 0; j < 8; j++) {
    int i = tid + j * kThreads;
    if (i < total) {
      int o = i >> 5, k = i & 31;
      r[j] = __ldg(W + o * Kfull + k0 + k);
    }
  }
}

__device__ __forceinline__ void sts_chunk(float* buf, const float (&r)[8],
                                          int On, int tid) {
  const int total = On * 32;
#pragma unroll
  for (int j = 0; j < 8; j++) {
    int i = tid + j * kThreads;
    if (i < total) {
      int o = i >> 5, k = i & 31;
      buf[o * WG_LD + k] = f2tf_f(r[j]);
    }
  }
}

// Staged matmul: acc += A[:, kbase' ...] @ W[:, kbase:kbase+32*nchunks]^T
// A chunk c uses A + c*32 columns. One __syncthreads per chunk.
template <int NT>
__device__ __forceinline__ void staged_mm(const float* A, int lda,
                                          const float* W, int On, int Kfull,
                                          int kbase, int nchunks,
                                          float (&d)[2][NT][4],
                                          float* wg0, float* wg1,
                                          int tid, int lane, int wm, int wn) {
  float r[8];
  ldg_chunk(r, W, On, Kfull, kbase, tid);
  sts_chunk(wg0, r, On, tid);
  __syncthreads();
  for (int c = 0; c < nchunks; c++) {
    float* cur = (c & 1) ? wg1 : wg0;
    float* nxt = (c & 1) ? wg0 : wg1;
    const bool more = (c + 1 < nchunks);
    if (more) ldg_chunk(r, W, On, Kfull, kbase + (c + 1) * 32, tid);
    mma_block<NT>(A + c * 32, lda, cur, WG_LD, 32, d, lane, wm, wn);
    if (more) sts_chunk(nxt, r, On, tid);
    __syncthreads();
  }
}

// ---- prologue kernel: Mt[j][i] = sum_d Wq[d][i] * Wk[d][j]
__global__ void precompute_mt(const float* __restrict__ Wq,
                              const float* __restrict__ Wk) {
  __shared__ float wkj[kD];
  const int j = blockIdx.x;
  const int i = threadIdx.x;
  wkj[i] = Wk[i * kD + j];
  __syncthreads();
  float s = 0.f;
#pragma unroll 8
  for (int dd = 0; dd < kD; dd++) s += Wq[dd * kD + i] * wkj[dd];
  gMt[j * kD + i] = s;
}

__global__ __launch_bounds__(kThreads, 1)
void critic_kernel(const float* __restrict__ states,
                   const float* __restrict__ actions,
                   const float* __restrict__ W_embed,
                   const float* __restrict__ b_embed,
                   const float* __restrict__ W_v,
                   const float* __restrict__ W_embed_q,
                   const float* __restrict__ b_embed_q,
                   const float* __restrict__ W_f1,
                   const float* __restrict__ W_f2,
                   float* __restrict__ outV,
                   float* __restrict__ outW) {
  extern __shared__ float smem[];
  const int b = blockIdx.x;
  const int tid = threadIdx.x;
  const int lane = tid & 31;
  const int warp = tid >> 5;
  const int wm = warp >> 3, wn = warp & 7;

  float* SA = smem + OFF_SA;
  float* T  = smem + OFF_T;
  float* SC = smem + OFF_SC;
  float* H  = smem + OFF_H;
  float* E  = smem + OFF_E;   // e, later x
  float* EQ = smem + OFF_EQ;
  float* VT = smem + OFF_VT;
  float* W0 = smem + OFF_W0;
  float* W1 = smem + OFF_W1;

  // ---- load sa = concat(states, actions), tf32-rounded
  {
    const float* st = states + (size_t)b * kN * kOBS;
    const float* ac = actions + (size_t)b * kN * kACT;
    for (int i = tid; i < kN * kIN; i += kThreads) {
      int t = i >> 8, c = i & 255;
      float v = (c < kOBS) ? st[t * kOBS + c] : ac[t * kACT + (c - kOBS)];
      SA[t * SA_LD + c] = f2tf_f(v);
    }
  }

  float d2[2][2][4];
  float d1[2][1][4];

  // ---- e = lrelu(sa @ W_embed^T + b_embed)  [64,128]
  zero_acc(d2);
  staged_mm<2>(SA, SA_LD, W_embed, 128, kIN, 0, 8, d2, W0, W1, tid, lane, wm, wn);
  for_each_acc<2>(d2, lane, wm, wn, [&](int r, int c, float v) {
    v += __ldg(b_embed + c);
    v = v > 0.f ? v : 0.01f * v;
    E[r * E_LD + c] = f2tf_f(v);
  });

  // ---- eq = lrelu(sa @ W_embed_q^T + b_embed_q)  [64,128]
  zero_acc(d2);
  staged_mm<2>(SA, SA_LD, W_embed_q, 128, kIN, 0, 8, d2, W0, W1, tid, lane, wm, wn);
  for_each_acc<2>(d2, lane, wm, wn, [&](int r, int c, float v) {
    v += __ldg(b_embed_q + c);
    v = v > 0.f ? v : 0.01f * v;
    EQ[r * E_LD + c] = f2tf_f(v);
  });
  __syncthreads();  // SA fully dead; T may now alias it

  // ---- t = e @ Mt^T  [64,128]   (Mt = (Wq^T Wk)^T, precomputed)
  zero_acc(d2);
  staged_mm<2>(E, E_LD, gMt, 128, kD, 0, 4, d2, W0, W1, tid, lane, wm, wn);
  for_each_acc<2>(d2, lane, wm, wn, [&](int r, int c, float v) {
    T[r * E_LD + c] = f2tf_f(v);
  });

  // ---- v = e @ W_v^T, stored transposed VT[d][m]  [128x64]
  zero_acc(d2);
  staged_mm<2>(E, E_LD, W_v, 128, kD, 0, 4, d2, W0, W1, tid, lane, wm, wn);
  for_each_acc<2>(d2, lane, wm, wn, [&](int r, int c, float v) {
    VT[c * S_LD + r] = f2tf_f(v);
  });
  __syncthreads();  // T, VT visible

  // ---- scores = t @ e^T / sqrt(D)  [64,64] -> SC (fp32)
  zero_acc(d1);
  mma_block<1>(T, E_LD, E, E_LD, kD, d1, lane, wm, wn);
  for_each_acc<1>(d1, lane, wm, wn, [&](int r, int c, float v) {
    SC[r * S_LD + c] = v * 0.08838834764831845f;
  });
  __syncthreads();

  // ---- row softmax; write weight to gmem (fp32) + tf32 copy in SC
  {
    const int r = tid >> 3;
    const int c0 = (tid & 7) * 8;
    float* wrow = SC + r * S_LD + c0;
    float mx = -3.0e38f;
#pragma unroll
    for (int j = 0; j < 8; j++) mx = fmaxf(mx, wrow[j]);
    mx = fmaxf(mx, __shfl_xor_sync(0xffffffffu, mx, 1));
    mx = fmaxf(mx, __shfl_xor_sync(0xffffffffu, mx, 2));
    mx = fmaxf(mx, __shfl_xor_sync(0xffffffffu, mx, 4));
    float ex[8];
    float sum = 0.f;
#pragma unroll
    for (int j = 0; j < 8; j++) {
      ex[j] = __expf(wrow[j] - mx);
      sum += ex[j];
    }
    sum += __shfl_xor_sync(0xffffffffu, sum, 1);
    sum += __shfl_xor_sync(0xffffffffu, sum, 2);
    sum += __shfl_xor_sync(0xffffffffu, sum, 4);
    float inv = 1.f / sum;
    float* og = outW + ((size_t)b * kN + r) * kN + c0;
#pragma unroll
    for (int j = 0; j < 8; j++) {
      float w = ex[j] * inv;
      og[j] = w;
      wrow[j] = f2tf_f(w);
    }
  }
  __syncthreads();

  // ---- x = weight @ v  [64,128]  (A=SC, B=VT) -> E region
  zero_acc(d2);
  mma_block<2>(SC, S_LD, VT, S_LD, kN, d2, lane, wm, wn);
  for_each_acc<2>(d2, lane, wm, wn, [&](int r, int c, float v) {
    E[r * E_LD + c] = f2tf_f(v);
  });
  __syncthreads();

  // ---- h = lrelu([eq, x] @ W_f1^T)  [64,64]
  zero_acc(d1);
  staged_mm<1>(EQ, E_LD, W_f1, 64, 2 * kD, 0, 4, d1, W0, W1, tid, lane, wm, wn);
  staged_mm<1>(E, E_LD, W_f1, 64, 2 * kD, kD, 4, d1, W0, W1, tid, lane, wm, wn);
  for_each_acc<1>(d1, lane, wm, wn, [&](int r, int c, float v) {
    v = v > 0.f ? v : 0.01f * v;
    H[r * S_LD + c] = f2tf_f(v);
  });

  // ---- Value = h @ W_f2^T -> gmem (fp32)
  zero_acc(d1);
  staged_mm<1>(H, S_LD, W_f2, 64, kFH, 0, 2, d1, W0, W1, tid, lane, wm, wn);
  for_each_acc<1>(d1, lane, wm, wn, [&](int r, int c, float v) {
    outV[((size_t)b * kN + r) * kFO + c] = v;
  });
}

}  // namespace

extern "C" void kernel_launch(void* const* d_in, const int* in_sizes, int n_in,
                              void* d_out, int out_size) {
  (void)in_sizes; (void)n_in; (void)out_size;
  const float* states    = (const float*)d_in[0];
  const float* actions   = (const float*)d_in[1];
  const float* W_embed   = (const float*)d_in[2];
  const float* b_embed   = (const float*)d_in[3];
  const float* W_k       = (const float*)d_in[4];
  const float* W_q       = (const float*)d_in[5];
  const float* W_v       = (const float*)d_in[6];
  const float* W_embed_q = (const float*)d_in[7];
  const float* b_embed_q = (const float*)d_in[8];
  const float* W_f1      = (const float*)d_in[9];
  const float* W_f2      = (const float*)d_in[10];

  float* outV = (float*)d_out;                 // Value [B,N,64] first
  float* outW = outV + (size_t)kB * kN * kFO;  // weight [B,N,N] second

  precompute_mt<<<kD, kD>>>(W_q, W_k);

  cudaFuncSetAttribute(critic_kernel,
                       cudaFuncAttributeMaxDynamicSharedMemorySize, SMEM_BYTES);
  critic_kernel<<<kB, kThreads, SMEM_BYTES>>>(states, actions, W_embed, b_embed,
                                              W_v, W_embed_q, b_embed_q,
                                              W_f1, W_f2, outV, outW);
}

// round 6
// speedup vs baseline: 1.9734x; 1.1229x over previous
#include <cuda_runtime.h>
#include <cstdint>
#include <cstddef>

namespace {

constexpr int kB   = 4096;
constexpr int kN   = 64;
constexpr int kOBS = 192;
constexpr int kACT = 64;
constexpr int kIN  = 256;
constexpr int kD   = 128;
constexpr int kFH  = 64;
constexpr int kFO  = 64;

constexpr int kThreads = 512;  // 16 warps

// strides ≡ 4 (mod 32): conflict-free scalar fragment loads (round-3 proven)
constexpr int SA_LD = 260;
constexpr int E_LD  = 132;
constexpr int S_LD  = 68;
constexpr int WG_LD = 36;

// SMEM pool (floats) — identical to round-3 passing kernel
constexpr int OFF_SA = 0;      // sa [64x260]=16640; later T(0..8448)+SC(8448..12800)
constexpr int OFF_T  = 0;      // t [64x132]; later H [64x68]
constexpr int OFF_SC = 8448;   // scores/weights [64x68]
constexpr int OFF_H  = 0;
constexpr int OFF_E  = 16640;  // e, later x [64x132]
constexpr int OFF_EQ = 25088;  // eq [64x132]
constexpr int OFF_VT = 33536;  // v^T [128x68] = 8704
constexpr int OFF_W0 = 42240;  // weight stage buf0 [128x36] = 4608
constexpr int OFF_W1 = 46848;  // weight stage buf1 [128x36] = 4608
constexpr int SMEM_FLOATS = 51456;
constexpr int SMEM_BYTES  = SMEM_FLOATS * 4;  // 205824

__device__ float gMt[kD * kD];  // gMt[j][i] = sum_d Wq[d][i]*Wk[d][j]

__device__ __forceinline__ float f2tf(float x) {
  uint32_t u;
  asm("cvt.rna.tf32.f32 %0, %1;" : "=r"(u) : "f"(x));
  return __uint_as_float(u);
}

__device__ __forceinline__ void mma8(float (&d)[4], const uint32_t (&a)[4],
                                     const uint32_t (&b)[2]) {
  asm volatile(
      "mma.sync.aligned.m16n8k8.row.col.f32.tf32.tf32.f32 "
      "{%0,%1,%2,%3}, {%4,%5,%6,%7}, {%8,%9}, {%0,%1,%2,%3};\n"
      : "+f"(d[0]), "+f"(d[1]), "+f"(d[2]), "+f"(d[3])
      : "r"(a[0]), "r"(a[1]), "r"(a[2]), "r"(a[3]), "r"(b[0]), "r"(b[1]));
}

// C[64 rows][NT*8 cols per warp] += A[64][KC] * B[cols][KC]^T
// identical to round-3 mma_block except KC is compile-time.
template <int NT, int KC>
__device__ __forceinline__ void mma_block(const float* __restrict__ As, int lda,
                                          const float* __restrict__ Bs, int ldb,
                                          float (&d)[2][NT][4],
                                          int lane, int wm, int wn) {
  const float* Aw = As + (wm * 32) * lda;
  const float* Bw = Bs + (wn * NT * 8) * ldb;
  const int gr = lane >> 2, gc = lane & 3;
#pragma unroll
  for (int k0 = 0; k0 < KC; k0 += 8) {
    uint32_t a[2][4];
#pragma unroll
    for (int mt = 0; mt < 2; mt++) {
      const float* p = Aw + (mt * 16 + gr) * lda + k0 + gc;
      a[mt][0] = __float_as_uint(p[0]);
      a[mt][1] = __float_as_uint(p[8 * lda]);
      a[mt][2] = __float_as_uint(p[4]);
      a[mt][3] = __float_as_uint(p[8 * lda + 4]);
    }
#pragma unroll
    for (int nt = 0; nt < NT; nt++) {
      const float* p = Bw + (nt * 8 + gr) * ldb + k0 + gc;
      uint32_t bf[2] = {__float_as_uint(p[0]), __float_as_uint(p[4])};
      mma8(d[0][nt], a[0], bf);
      mma8(d[1][nt], a[1], bf);
    }
  }
}

template <int NT, class F>
__device__ __forceinline__ void for_each(float (&d)[2][NT][4], int lane,
                                         int wm, int wn, F f) {
  const int gr = lane >> 2, gc = (lane & 3) * 2;
#pragma unroll
  for (int mt = 0; mt < 2; mt++)
#pragma unroll
    for (int nt = 0; nt < NT; nt++)
#pragma unroll
      for (int i = 0; i < 4; i++) {
        int row = wm * 32 + mt * 16 + gr + ((i >> 1) << 3);
        int col = wn * NT * 8 + nt * 8 + gc + (i & 1);
        f(row, col, d[mt][nt][i]);
      }
}

template <int NT>
__device__ __forceinline__ void zero_acc(float (&d)[2][NT][4]) {
#pragma unroll
  for (int mt = 0; mt < 2; mt++)
#pragma unroll
    for (int nt = 0; nt < NT; nt++)
#pragma unroll
      for (int i = 0; i < 4; i++) d[mt][nt][i] = 0.f;
}

// ---- weight chunk staging: all 512 threads stage [On x 32] (round-3 verbatim)
__device__ __forceinline__ void ldg_chunk(float (&r)[8], const float* __restrict__ W,
                                          int On, int Kfull, int k0, int tid) {
  const int total = On * 32;
#pragma unroll
  for (int j = 0; j < 8; j++) {
    int i = tid + j * kThreads;
    if (i < total) {
      int o = i >> 5, k = i & 31;
      r[j] = __ldg(W + o * Kfull + k0 + k);
    }
  }
}

__device__ __forceinline__ void sts_chunk(float* buf, const float (&r)[8],
                                          int On, int tid) {
  const int total = On * 32;
#pragma unroll
  for (int j = 0; j < 8; j++) {
    int i = tid + j * kThreads;
    if (i < total) {
      int o = i >> 5, k = i & 31;
      buf[o * WG_LD + k] = f2tf(r[j]);
    }
  }
}

// Double-buffered staged matmul (round-3 verbatim structure; NCH compile-time;
// mma guarded by `active` — all barriers outside the conditional).
template <int NT, int NCH>
__device__ __forceinline__ void staged_mm(const float* __restrict__ A, int lda,
                                          const float* __restrict__ W, int On,
                                          int Kfull, int kbase,
                                          float (&d)[2][NT][4],
                                          float* wg0, float* wg1, int tid,
                                          int lane, int wm, int wn,
                                          bool active) {
  float r[8];
  ldg_chunk(r, W, On, Kfull, kbase, tid);
  sts_chunk(wg0, r, On, tid);
  __syncthreads();
#pragma unroll
  for (int c = 0; c < NCH; c++) {
    float* cur = (c & 1) ? wg1 : wg0;
    float* nxt = (c & 1) ? wg0 : wg1;
    const bool more = (c + 1 < NCH);
    if (more) ldg_chunk(r, W, On, Kfull, kbase + (c + 1) * 32, tid);
    if (active) mma_block<NT, 32>(A + c * 32, lda, cur, WG_LD, d, lane, wm, wn);
    if (more) sts_chunk(nxt, r, On, tid);
    __syncthreads();
  }
}

// ---- prologue: gMt[j][i] = sum_d Wq[d][i]*Wk[d][j]
__global__ void precompute_mt(const float* __restrict__ Wq,
                              const float* __restrict__ Wk) {
  __shared__ float wkj[kD];
  const int j = blockIdx.x;
  const int i = threadIdx.x;
  wkj[i] = Wk[i * kD + j];
  __syncthreads();
  float s = 0.f;
#pragma unroll 8
  for (int dd = 0; dd < kD; dd++) s += Wq[dd * kD + i] * wkj[dd];
  gMt[j * kD + i] = s;
}

__global__ __launch_bounds__(kThreads, 1)
void critic_kernel(const float* __restrict__ states,
                   const float* __restrict__ actions,
                   const float* __restrict__ W_embed,
                   const float* __restrict__ b_embed,
                   const float* __restrict__ W_v,
                   const float* __restrict__ W_embed_q,
                   const float* __restrict__ b_embed_q,
                   const float* __restrict__ W_f1,
                   const float* __restrict__ W_f2,
                   float* __restrict__ outV,
                   float* __restrict__ outW) {
  extern __shared__ float smem[];
  const int b = blockIdx.x;
  const int tid = threadIdx.x;
  const int lane = tid & 31;
  const int warp = tid >> 5;
  // 16-warp grid (scores/x/f1/Value stages — round-3 proven)
  const int wm16 = warp >> 3, wn16 = warp & 7;
  // 8-warp grid with 32x32 tiles (e/eq/t/v stages — round-2 proven tile math)
  const int wm8 = (warp >> 2) & 1, wn8 = warp & 3;
  const bool act8 = (warp < 8);

  float* SA = smem + OFF_SA;
  float* T  = smem + OFF_T;
  float* SC = smem + OFF_SC;
  float* H  = smem + OFF_H;
  float* E  = smem + OFF_E;
  float* EQ = smem + OFF_EQ;
  float* VT = smem + OFF_VT;
  float* W0 = smem + OFF_W0;
  float* W1 = smem + OFF_W1;

  // ---- load sa (visibility covered by first staged_mm barrier)
  {
    const float* st = states + (size_t)b * kN * kOBS;
    const float* ac = actions + (size_t)b * kN * kACT;
#pragma unroll 4
    for (int j = 0; j < 32; j++) {
      int i = tid + j * kThreads;
      int t = i >> 8, c = i & 255;
      float v = (c < kOBS) ? st[t * kOBS + c] : ac[t * kACT + (c - kOBS)];
      SA[t * SA_LD + c] = f2tf(v);
    }
  }

  float d4[2][4][4];
  float d2[2][2][4];
  float d1[2][1][4];

  // ---- e = lrelu(sa @ W_embed^T + b_embed)  [64,128]  (warps 0-7, 32x32)
  zero_acc(d4);
  staged_mm<4, 8>(SA, SA_LD, W_embed, 128, kIN, 0, d4, W0, W1, tid, lane,
                  wm8, wn8, act8);
  if (act8)
    for_each<4>(d4, lane, wm8, wn8, [&](int r, int c, float v) {
      v += __ldg(b_embed + c);
      v = v > 0.f ? v : 0.01f * v;
      E[r * E_LD + c] = f2tf(v);
    });

  // ---- eq = lrelu(sa @ W_embed_q^T + b_embed_q)  [64,128]
  zero_acc(d4);
  staged_mm<4, 8>(SA, SA_LD, W_embed_q, 128, kIN, 0, d4, W0, W1, tid, lane,
                  wm8, wn8, act8);
  if (act8)
    for_each<4>(d4, lane, wm8, wn8, [&](int r, int c, float v) {
      v += __ldg(b_embed_q + c);
      v = v > 0.f ? v : 0.01f * v;
      EQ[r * E_LD + c] = f2tf(v);
    });
  __syncthreads();  // SA fully dead; T may now alias it

  // ---- t = e @ Mt^T  [64,128]
  zero_acc(d4);
  staged_mm<4, 4>(E, E_LD, gMt, 128, kD, 0, d4, W0, W1, tid, lane,
                  wm8, wn8, act8);
  if (act8)
    for_each<4>(d4, lane, wm8, wn8, [&](int r, int c, float v) {
      T[r * E_LD + c] = f2tf(v);
    });

  // ---- v = e @ W_v^T, stored transposed VT[d][m]  [128x64]
  zero_acc(d4);
  staged_mm<4, 4>(E, E_LD, W_v, 128, kD, 0, d4, W0, W1, tid, lane,
                  wm8, wn8, act8);
  if (act8)
    for_each<4>(d4, lane, wm8, wn8, [&](int r, int c, float v) {
      VT[c * S_LD + r] = f2tf(v);
    });
  __syncthreads();  // T, VT visible to all warps

  // ---- scores = t @ e^T / sqrt(D)  [64,64] -> SC  (16 warps, round-3 verbatim)
  zero_acc(d1);
  mma_block<1, 128>(T, E_LD, E, E_LD, d1, lane, wm16, wn16);
  for_each<1>(d1, lane, wm16, wn16, [&](int r, int c, float v) {
    SC[r * S_LD + c] = v * 0.08838834764831845f;
  });
  __syncthreads();

  // ---- row softmax: gmem fp32 + tf32 back into SC (round-3 verbatim)
  {
    const int r = tid >> 3;
    const int c0 = (tid & 7) * 8;
    float* wrow = SC + r * S_LD + c0;
    float s[8];
#pragma unroll
    for (int j = 0; j < 8; j++) s[j] = wrow[j];
    float mx = -3.0e38f;
#pragma unroll
    for (int j = 0; j < 8; j++) mx = fmaxf(mx, s[j]);
    mx = fmaxf(mx, __shfl_xor_sync(0xffffffffu, mx, 1));
    mx = fmaxf(mx, __shfl_xor_sync(0xffffffffu, mx, 2));
    mx = fmaxf(mx, __shfl_xor_sync(0xffffffffu, mx, 4));
    float sum = 0.f;
#pragma unroll
    for (int j = 0; j < 8; j++) {
      s[j] = __expf(s[j] - mx);
      sum += s[j];
    }
    sum += __shfl_xor_sync(0xffffffffu, sum, 1);
    sum += __shfl_xor_sync(0xffffffffu, sum, 2);
    sum += __shfl_xor_sync(0xffffffffu, sum, 4);
    float inv = 1.f / sum;
    float* og = outW + ((size_t)b * kN + r) * kN + c0;
#pragma unroll
    for (int j = 0; j < 8; j++) {
      float wv = s[j] * inv;
      og[j] = wv;
      wrow[j] = f2tf(wv);
    }
  }
  __syncthreads();

  // ---- x = weight @ v  [64,128]  (16 warps) -> E region (e is dead)
  zero_acc(d2);
  mma_block<2, 64>(SC, S_LD, VT, S_LD, d2, lane, wm16, wn16);
  for_each<2>(d2, lane, wm16, wn16, [&](int r, int c, float v) {
    E[r * E_LD + c] = f2tf(v);
  });
  __syncthreads();

  // ---- h = lrelu([eq, x] @ W_f1^T)  [64,64]  (16 warps, accumulate halves)
  zero_acc(d1);
  staged_mm<1, 4>(EQ, E_LD, W_f1, 64, 2 * kD, 0, d1, W0, W1, tid, lane,
                  wm16, wn16, true);
  staged_mm<1, 4>(E, E_LD, W_f1, 64, 2 * kD, kD, d1, W0, W1, tid, lane,
                  wm16, wn16, true);
  for_each<1>(d1, lane, wm16, wn16, [&](int r, int c, float v) {
    v = v > 0.f ? v : 0.01f * v;
    H[r * S_LD + c] = f2tf(v);
  });

  // ---- Value = h @ W_f2^T -> gmem (staged_mm's first barrier covers H)
  zero_acc(d1);
  staged_mm<1, 2>(H, S_LD, W_f2, 64, kFH, 0, d1, W0, W1, tid, lane,
                  wm16, wn16, true);
  for_each<1>(d1, lane, wm16, wn16, [&](int r, int c, float v) {
    outV[((size_t)b * kN + r) * kFO + c] = v;
  });
}

}  // namespace

extern "C" void kernel_launch(void* const* d_in, const int* in_sizes, int n_in,
                              void* d_out, int out_size) {
  (void)in_sizes; (void)n_in; (void)out_size;
  const float* states    = (const float*)d_in[0];
  const float* actions   = (const float*)d_in[1];
  const float* W_embed   = (const float*)d_in[2];
  const float* b_embed   = (const float*)d_in[3];
  const float* W_k       = (const float*)d_in[4];
  const float* W_q       = (const float*)d_in[5];
  const float* W_v       = (const float*)d_in[6];
  const float* W_embed_q = (const float*)d_in[7];
  const float* b_embed_q = (const float*)d_in[8];
  const float* W_f1      = (const float*)d_in[9];
  const float* W_f2      = (const float*)d_in[10];

  float* outV = (float*)d_out;                 // Value [B,N,64]
  float* outW = outV + (size_t)kB * kN * kFO;  // weight [B,N,N]

  precompute_mt<<<kD, kD>>>(W_q, W_k);

  cudaFuncSetAttribute(critic_kernel,
                       cudaFuncAttributeMaxDynamicSharedMemorySize, SMEM_BYTES);
  critic_kernel<<<kB, kThreads, SMEM_BYTES>>>(states, actions, W_embed,
                                              b_embed, W_v, W_embed_q,
                                              b_embed_q, W_f1, W_f2,
                                              outV, outW);
}